// round 7
// baseline (speedup 1.0000x reference)
#include <cuda_runtime.h>
#include <cuda_bf16.h>
#include <math.h>
#include <stdint.h>

#define BB 8
#define NN 2048
#define KK 1024
#define NP 64            // points per block

// ---------------- device state ----------------
__device__ float d_mean0[BB*3], d_mean1[BB*3];
__device__ float d_posesJ[7*12];
__device__ float d_gpose[BB*12];
__device__ float d_igtinv[BB*12];
__device__ float d_estg[BB*12];
__device__ float d_f0[BB*KK], d_fj[BB*6*KK], d_f1[BB*KK];
__device__ float d_J[BB*KK*6];
__device__ float d_Hinv[BB*36];
__device__ float d_r[BB*KK];
__device__ float d_lpart[64];

typedef unsigned long long u64;

// ---------------- helpers ----------------
__device__ __forceinline__ void atomicMaxF(float* addr, float val) {
    if (val >= 0.f) atomicMax((int*)addr, __float_as_int(val));
    else            atomicMin((unsigned int*)addr, __float_as_uint(val));
}
__device__ __forceinline__ void unpk2(u64 v, float& a, float& b) {
    asm("mov.b64 {%0,%1},%2;" : "=f"(a), "=f"(b) : "l"(v));
}
__device__ __forceinline__ void fma2(u64& d, u64 a, u64 b) {
    asm("fma.rn.f32x2 %0,%1,%2,%0;" : "+l"(d) : "l"(a), "l"(b));
}
__device__ __forceinline__ void cp16(uint32_t dst, const void* src) {
    asm volatile("cp.async.cg.shared.global [%0], [%1], 16;\n" :: "r"(dst), "l"(src));
}
#define CP_COMMIT() asm volatile("cp.async.commit_group;\n" ::: "memory")

// se3_exp (double internals), output 3x4 row-major float
__device__ void se3_exp_d(const double w[3], const double v[3], float out[12]) {
    double t2 = w[0]*w[0] + w[1]*w[1] + w[2]*w[2];
    double t = sqrt(t2);
    double A, Bc, Cc;
    if (t < 1e-6) {
        A  = 1.0 - t2/6.0;  Bc = 0.5 - t2/24.0;  Cc = 1.0/6.0 - t2/120.0;
    } else {
        double st = sin(t), ct = cos(t);
        A = st/t;  Bc = (1.0-ct)/t2;  Cc = (t-st)/(t2*t);
    }
    double W[3][3] = {{0.0,-w[2],w[1]},{w[2],0.0,-w[0]},{-w[1],w[0],0.0}};
    double W2m[3][3];
    for (int i = 0; i < 3; i++)
        for (int j = 0; j < 3; j++)
            W2m[i][j] = w[i]*w[j] - (i==j ? t2 : 0.0);
    double R[3][3], V[3][3];
    for (int i = 0; i < 3; i++)
        for (int j = 0; j < 3; j++) {
            double I = (i==j) ? 1.0 : 0.0;
            R[i][j] = I + A*W[i][j] + Bc*W2m[i][j];
            V[i][j] = I + Bc*W[i][j] + Cc*W2m[i][j];
        }
    for (int i = 0; i < 3; i++) {
        double p = V[i][0]*v[0] + V[i][1]*v[1] + V[i][2]*v[2];
        out[i*4+0] = (float)R[i][0]; out[i*4+1] = (float)R[i][1];
        out[i*4+2] = (float)R[i][2]; out[i*4+3] = (float)p;
    }
}

// ---------------- means ----------------
__global__ void means_kernel(const float* __restrict__ p_tgt, const float* __restrict__ p_src) {
    int b = blockIdx.x, tid = threadIdx.x;
    float a[6] = {0,0,0,0,0,0};
    for (int n = tid; n < NN; n += 256) {
        const float* pt = p_tgt + ((size_t)b*NN + n)*3;
        const float* ps = p_src + ((size_t)b*NN + n)*3;
        a[0] += pt[0]; a[1] += pt[1]; a[2] += pt[2];
        a[3] += ps[0]; a[4] += ps[1]; a[5] += ps[2];
    }
    for (int off = 16; off; off >>= 1)
        #pragma unroll
        for (int q = 0; q < 6; q++) a[q] += __shfl_down_sync(0xffffffffu, a[q], off);
    __shared__ float sm[8][6];
    int lane = tid & 31, w = tid >> 5;
    if (lane == 0) { for (int q = 0; q < 6; q++) sm[w][q] = a[q]; }
    __syncthreads();
    if (tid < 6) {
        float s = 0.f;
        for (int w2 = 0; w2 < 8; w2++) s += sm[w2][tid];
        s *= (1.0f / NN);
        if (tid < 3) d_mean0[b*3 + tid] = s;
        else         d_mean1[b*3 + tid - 3] = s;
    }
}

// ---------------- setup ----------------
__global__ void setup_kernel(const float* __restrict__ dt, const float* __restrict__ igt_twist) {
    int tid = threadIdx.x;
    if (tid < 7) {
        float out[12];
        if (tid == 0) {
            float I[12] = {1,0,0,0, 0,1,0,0, 0,0,1,0};
            for (int i = 0; i < 12; i++) out[i] = I[i];
        } else {
            int j = tid - 1;
            double w[3] = {0,0,0}, v[3] = {0,0,0};
            double val = -(double)__ldg(&dt[j]);
            if (j < 3) w[j] = val; else v[j-3] = val;
            se3_exp_d(w, v, out);
        }
        for (int i = 0; i < 12; i++) d_posesJ[tid*12 + i] = out[i];
    }
    if (tid >= 8 && tid < 16) {
        int b = tid - 8;
        float I[12] = {1,0,0,0, 0,1,0,0, 0,0,1,0};
        for (int i = 0; i < 12; i++) d_gpose[b*12 + i] = I[i];
    }
    if (tid >= 16 && tid < 24) {
        int b = tid - 16;
        double w[3], v[3];
        for (int i = 0; i < 3; i++) { w[i] = igt_twist[b*6 + i]; v[i] = igt_twist[b*6 + 3 + i]; }
        float g[12];
        se3_exp_d(w, v, g);
        float inv[12];
        for (int r = 0; r < 3; r++)
            for (int c = 0; c < 3; c++) inv[r*4 + c] = g[c*4 + r];
        for (int r = 0; r < 3; r++)
            inv[r*4 + 3] = -(g[0*4+r]*g[3] + g[1*4+r]*g[7] + g[2*4+r]*g[11]);
        for (int i = 0; i < 12; i++) d_igtinv[b*12 + i] = inv[i];
    }
}

// init f0, fj, f1 to -INF
__global__ void init_f_kernel() {
    int i = blockIdx.x*256 + threadIdx.x;
    if (i < BB*KK) d_f0[i] = -INFINITY;
    else if (i < BB*KK + BB*6*KK) d_fj[i - BB*KK] = -INFINITY;
    else if (i < BB*KK + BB*6*KK + BB*KK) d_f1[i - BB*KK - BB*6*KK] = -INFINITY;
}

// ---------------- fused encode ----------------
// 256 threads, 64 points. K in 4 passes of 256 cols; each pass = 8 c-tiles
// (16 c x 256 k, 16KB), double-buffered cp.async.
// h2 stored PRE-DUPLICATED ([h,h] pairs): both FFMA2 operands load as natural
// u64 pairs from SMEM -> zero MOV dups in the inner loop.
// Thread micro-tile: 8p x 8k. Warp: 8 p-lanes x 4 k-lanes = 64p x 32k.
// SMEM (floats):
//   WB0 [0,4096), WB1 [4096,8192)         W3 tiles (A-phase alias: pts/W1/b1/b2/H1)
//   H2D [8192,24576) 128 c x 128 floats   dup'd h2 (A-phase alias: W2 at [8192,16384))
#define OFF_WB0  0
#define OFF_WB1  4096
#define OFF_PTS  0
#define OFF_SW1  192
#define OFF_SB1  384
#define OFF_SB2  448
#define OFF_H1   576            /* 64 x 68 -> ends 4928 < 8192 */
#define OFF_W2   8192           /* alias under H2D, consumed before H2D writes */
#define OFF_H2D  8192           /* 128 c x 128 floats = 16384 */
#define STRH2    128
#define SMEMF    24576
#define SMEM_BYTES (SMEMF*4)

// Stage tile t (t = kp*8 + ct): rows c = ct*16..+15, cols k = kp*256..+255.
__device__ __forceinline__ void issue_tile(uint32_t sbase, int t,
                                           const float* __restrict__ W3g, int tid) {
    int kp = t >> 3, ct = t & 7;
    uint32_t buf = sbase + (uint32_t)(t & 1) * (4096u * 4u);
    const float* src = W3g + (size_t)(ct*16)*1024 + kp*256;
    #pragma unroll
    for (int i = 0; i < 4; i++) {
        int f4 = i*256 + tid;              // 1024 float4 total
        int row = f4 >> 6, col4 = f4 & 63; // 64 float4 per row
        cp16(buf + (uint32_t)(row*256 + col4*4)*4u, src + (size_t)row*1024 + col4*4);
    }
}

template<int MODE>
__global__ __launch_bounds__(256, 2)
void encode_kernel(const float* __restrict__ P,
                   const float* __restrict__ W1g, const float* __restrict__ b1g,
                   const float* __restrict__ W2g, const float* __restrict__ b2g,
                   const float* __restrict__ W3g, const float* __restrict__ b3g) {
    extern __shared__ float sm[];
    int tid = threadIdx.x;
    uint32_t sbase = (uint32_t)__cvta_generic_to_shared(sm);

    int b; const float* pose; const float* mean; float* out;
    if (MODE == 0) {
        int bm = blockIdx.y;
        b = bm / 7; int m = bm % 7;
        pose = d_posesJ + m*12;
        mean = d_mean0 + b*3;
        out  = (m == 0) ? (d_f0 + b*KK) : (d_fj + ((size_t)b*6 + (m-1))*KK);
    } else {
        b = blockIdx.y;
        pose = d_gpose + b*12;
        mean = d_mean1 + b*3;
        out  = d_f1 + b*KK;
    }

    // phase A0: stage weights + transform points
    {
        const float4* w2v = (const float4*)W2g;
        #pragma unroll
        for (int i = 0; i < 8; i++)
            *(float4*)&sm[OFF_W2 + (tid + i*256)*4] = w2v[tid + i*256];
    }
    if (tid >= 64 && tid < 256) sm[OFF_SW1 + tid - 64] = W1g[tid - 64];
    if (tid < 64)  sm[OFF_SB1 + tid] = b1g[tid];
    if (tid >= 64 && tid < 192) sm[OFF_SB2 + tid - 64] = b2g[tid - 64];
    if (tid < NP) {
        int n = blockIdx.x * NP + tid;
        const float* pp = P + ((size_t)b*NN + n)*3;
        float dx = pp[0] - mean[0], dy = pp[1] - mean[1], dz = pp[2] - mean[2];
        sm[OFF_PTS + tid*3 + 0] = pose[0]*dx + pose[1]*dy + pose[2]*dz  + pose[3];
        sm[OFF_PTS + tid*3 + 1] = pose[4]*dx + pose[5]*dy + pose[6]*dz  + pose[7];
        sm[OFF_PTS + tid*3 + 2] = pose[8]*dx + pose[9]*dy + pose[10]*dz + pose[11];
    }
    __syncthreads();

    // phase A1: h1 = relu(pt @ W1 + b1), 64 x 64 (stride 68)
    #pragma unroll
    for (int i = 0; i < 16; i++) {
        int idx = tid + i*256;
        int p = idx >> 6, c1 = idx & 63;
        float x = sm[OFF_PTS + p*3 + 0], y = sm[OFF_PTS + p*3 + 1], z = sm[OFF_PTS + p*3 + 2];
        float v = sm[OFF_SB1 + c1];
        v = fmaf(x, sm[OFF_SW1 + c1],       v);
        v = fmaf(y, sm[OFF_SW1 + 64 + c1],  v);
        v = fmaf(z, sm[OFF_SW1 + 128 + c1], v);
        sm[OFF_H1 + p*68 + c1] = fmaxf(v, 0.f);
    }
    __syncthreads();

    // phase A2: compute h2 for this thread's (p, 32 c2) into registers,
    // sync, then write DUPLICATED rows over the W2 alias region.
    float vreg[32];
    {
        int p = tid >> 2, r = tid & 3;
        float hr[64];
        #pragma unroll
        for (int i = 0; i < 16; i++) {
            float4 h4 = *(const float4*)&sm[OFF_H1 + p*68 + i*4];
            hr[i*4+0] = h4.x; hr[i*4+1] = h4.y; hr[i*4+2] = h4.z; hr[i*4+3] = h4.w;
        }
        #pragma unroll
        for (int q = 0; q < 8; q++) {
            int c2 = r*4 + q*16;
            float4 acc = *(const float4*)&sm[OFF_SB2 + c2];
            #pragma unroll 16
            for (int c1 = 0; c1 < 64; c1++) {
                float4 w = *(const float4*)&sm[OFF_W2 + c1*128 + c2];
                float h = hr[c1];
                acc.x = fmaf(h, w.x, acc.x); acc.y = fmaf(h, w.y, acc.y);
                acc.z = fmaf(h, w.z, acc.z); acc.w = fmaf(h, w.w, acc.w);
            }
            vreg[q*4+0] = fmaxf(acc.x, 0.f);
            vreg[q*4+1] = fmaxf(acc.y, 0.f);
            vreg[q*4+2] = fmaxf(acc.z, 0.f);
            vreg[q*4+3] = fmaxf(acc.w, 0.f);
        }
    }
    __syncthreads();   // all W2 reads done
    {
        int p = tid >> 2, r = tid & 3;
        #pragma unroll
        for (int q = 0; q < 8; q++)
            #pragma unroll
            for (int j = 0; j < 4; j++) {
                int c2 = r*4 + q*16 + j;
                float v = vreg[q*4+j];
                *(float2*)&sm[OFF_H2D + c2*STRH2 + 2*p] = make_float2(v, v);
            }
    }
    __syncthreads();   // H2D ready; WB region free

    issue_tile(sbase, 0, W3g, tid); CP_COMMIT();
    issue_tile(sbase, 1, W3g, tid); CP_COMMIT();

    // phase B: 32 tiles (4 k-passes x 8 c-tiles of 16 c)
    int lane = tid & 31, w = tid >> 5;
    int pl = lane & 7, kl = lane >> 3;
    const float* hbase = &sm[OFF_H2D + pl*16];   // dup'd points 8pl..8pl+7
    u64 acc[8][4];                               // [point][k-pair]

    for (int t = 0; t < 32; t++) {
        int kp = t >> 3, ct = t & 7;
        if (t < 31) asm volatile("cp.async.wait_group 1;\n" ::: "memory");
        else        asm volatile("cp.async.wait_group 0;\n" ::: "memory");
        __syncthreads();

        if (ct == 0) {
            #pragma unroll
            for (int i = 0; i < 8; i++)
                #pragma unroll
                for (int j = 0; j < 4; j++) acc[i][j] = 0ull;
        }

        const float* wb = &sm[(t & 1) ? OFF_WB1 : OFF_WB0] + w*32 + kl*8;
        const float* hrow = hbase + (ct*16)*STRH2;

        #pragma unroll 4
        for (int c = 0; c < 16; c++) {
            ulonglong2 h01 = *(const ulonglong2*)&hrow[c*STRH2];
            ulonglong2 h23 = *(const ulonglong2*)&hrow[c*STRH2 + 4];
            ulonglong2 h45 = *(const ulonglong2*)&hrow[c*STRH2 + 8];
            ulonglong2 h67 = *(const ulonglong2*)&hrow[c*STRH2 + 12];
            ulonglong2 wA = *(const ulonglong2*)&wb[c*256];
            ulonglong2 wB = *(const ulonglong2*)&wb[c*256 + 4];
            fma2(acc[0][0], h01.x, wA.x); fma2(acc[0][1], h01.x, wA.y);
            fma2(acc[0][2], h01.x, wB.x); fma2(acc[0][3], h01.x, wB.y);
            fma2(acc[1][0], h01.y, wA.x); fma2(acc[1][1], h01.y, wA.y);
            fma2(acc[1][2], h01.y, wB.x); fma2(acc[1][3], h01.y, wB.y);
            fma2(acc[2][0], h23.x, wA.x); fma2(acc[2][1], h23.x, wA.y);
            fma2(acc[2][2], h23.x, wB.x); fma2(acc[2][3], h23.x, wB.y);
            fma2(acc[3][0], h23.y, wA.x); fma2(acc[3][1], h23.y, wA.y);
            fma2(acc[3][2], h23.y, wB.x); fma2(acc[3][3], h23.y, wB.y);
            fma2(acc[4][0], h45.x, wA.x); fma2(acc[4][1], h45.x, wA.y);
            fma2(acc[4][2], h45.x, wB.x); fma2(acc[4][3], h45.x, wB.y);
            fma2(acc[5][0], h45.y, wA.x); fma2(acc[5][1], h45.y, wA.y);
            fma2(acc[5][2], h45.y, wB.x); fma2(acc[5][3], h45.y, wB.y);
            fma2(acc[6][0], h67.x, wA.x); fma2(acc[6][1], h67.x, wA.y);
            fma2(acc[6][2], h67.x, wB.x); fma2(acc[6][3], h67.x, wB.y);
            fma2(acc[7][0], h67.y, wA.x); fma2(acc[7][1], h67.y, wA.y);
            fma2(acc[7][2], h67.y, wB.x); fma2(acc[7][3], h67.y, wB.y);
        }
        __syncthreads();   // done reading buf[t&1]
        if (t + 2 < 32) { issue_tile(sbase, t + 2, W3g, tid); CP_COMMIT(); }

        if (ct == 7) {
            float mx[8];
            #pragma unroll
            for (int kp2 = 0; kp2 < 4; kp2++) {
                float me = -INFINITY, mo = -INFINITY;
                #pragma unroll
                for (int p = 0; p < 8; p++) {
                    float lo, hi;
                    unpk2(acc[p][kp2], lo, hi);
                    me = fmaxf(me, lo); mo = fmaxf(mo, hi);
                }
                mx[2*kp2]   = me;
                mx[2*kp2+1] = mo;
            }
            #pragma unroll
            for (int off = 1; off < 8; off <<= 1)
                #pragma unroll
                for (int j = 0; j < 8; j++)
                    mx[j] = fmaxf(mx[j], __shfl_xor_sync(0xffffffffu, mx[j], off));
            int k = kp*256 + w*32 + kl*8 + pl;
            atomicMaxF(&out[k], mx[pl] + __ldg(&b3g[k]));
        }
    }
}

// ---------------- J and Hinv ----------------
__global__ void jh_kernel(const float* __restrict__ dt) {
    int b = blockIdx.x, tid = threadIdx.x;
    float dtv[6];
    #pragma unroll
    for (int j = 0; j < 6; j++) dtv[j] = __ldg(&dt[j]);
    double hacc[21];
    #pragma unroll
    for (int q = 0; q < 21; q++) hacc[q] = 0.0;
    for (int k = tid; k < KK; k += 256) {
        float f0k = d_f0[b*KK + k];
        float jv[6];
        #pragma unroll
        for (int j = 0; j < 6; j++) {
            jv[j] = (f0k - d_fj[((size_t)b*6 + j)*KK + k]) / dtv[j];
            d_J[((size_t)b*KK + k)*6 + j] = jv[j];
        }
        int q = 0;
        #pragma unroll
        for (int i = 0; i < 6; i++)
            #pragma unroll
            for (int j = i; j < 6; j++)
                hacc[q++] += (double)jv[i] * (double)jv[j];
    }
    for (int off = 16; off; off >>= 1)
        #pragma unroll
        for (int q = 0; q < 21; q++) hacc[q] += __shfl_down_sync(0xffffffffu, hacc[q], off);
    __shared__ double shH[8][21];
    int lane = tid & 31, w = tid >> 5;
    if (lane == 0) { for (int q = 0; q < 21; q++) shH[w][q] = hacc[q]; }
    __syncthreads();
    if (tid == 0) {
        double s[21];
        for (int q = 0; q < 21; q++) { s[q] = 0.0; for (int w2 = 0; w2 < 8; w2++) s[q] += shH[w2][q]; }
        double H[6][6];
        int q = 0;
        for (int i = 0; i < 6; i++)
            for (int j = i; j < 6; j++) { H[i][j] = s[q]; H[j][i] = s[q]; q++; }
        double M[6][12];
        for (int i = 0; i < 6; i++)
            for (int j = 0; j < 12; j++) M[i][j] = (j < 6) ? H[i][j] : ((j - 6 == i) ? 1.0 : 0.0);
        for (int col = 0; col < 6; col++) {
            int piv = col; double best = fabs(M[col][col]);
            for (int r2 = col + 1; r2 < 6; r2++)
                if (fabs(M[r2][col]) > best) { best = fabs(M[r2][col]); piv = r2; }
            if (piv != col)
                for (int j = 0; j < 12; j++) { double t = M[col][j]; M[col][j] = M[piv][j]; M[piv][j] = t; }
            double inv = 1.0 / M[col][col];
            for (int j = 0; j < 12; j++) M[col][j] *= inv;
            for (int r2 = 0; r2 < 6; r2++) {
                if (r2 == col) continue;
                double f = M[r2][col];
                for (int j = 0; j < 12; j++) M[r2][j] -= f * M[col][j];
            }
        }
        for (int i = 0; i < 6; i++)
            for (int j = 0; j < 6; j++) d_Hinv[b*36 + i*6 + j] = (float)M[i][6 + j];
    }
}

// ---------------- Gauss-Newton update (also resets f1 for next iter) ----------------
__global__ void update_kernel() {
    int b = blockIdx.x, tid = threadIdx.x;
    double u[6] = {0,0,0,0,0,0};
    for (int k = tid; k < KK; k += 256) {
        float r = d_f1[b*KK + k] - d_f0[b*KK + k];
        d_r[b*KK + k] = r;
        d_f1[b*KK + k] = -INFINITY;   // reset for next encode<1>
        #pragma unroll
        for (int j = 0; j < 6; j++) u[j] += (double)d_J[((size_t)b*KK + k)*6 + j] * (double)r;
    }
    for (int off = 16; off; off >>= 1)
        #pragma unroll
        for (int j = 0; j < 6; j++) u[j] += __shfl_down_sync(0xffffffffu, u[j], off);
    __shared__ double shU[8][6];
    int lane = tid & 31, w = tid >> 5;
    if (lane == 0) { for (int j = 0; j < 6; j++) shU[w][j] = u[j]; }
    __syncthreads();
    if (tid == 0) {
        double uu[6];
        for (int j = 0; j < 6; j++) { uu[j] = 0.0; for (int w2 = 0; w2 < 8; w2++) uu[j] += shU[w2][j]; }
        double dx[6];
        for (int i = 0; i < 6; i++) {
            double s2 = 0.0;
            for (int j = 0; j < 6; j++) s2 += (double)d_Hinv[b*36 + i*6 + j] * uu[j];
            dx[i] = -s2;
        }
        float E[12];
        double wv[3] = {dx[0], dx[1], dx[2]}, vv[3] = {dx[3], dx[4], dx[5]};
        se3_exp_d(wv, vv, E);
        float G[12];
        for (int i = 0; i < 12; i++) G[i] = d_gpose[b*12 + i];
        float Ng[12];
        for (int r2 = 0; r2 < 3; r2++) {
            for (int c = 0; c < 3; c++)
                Ng[r2*4 + c] = E[r2*4+0]*G[0*4+c] + E[r2*4+1]*G[1*4+c] + E[r2*4+2]*G[2*4+c];
            Ng[r2*4 + 3] = E[r2*4+0]*G[3] + E[r2*4+1]*G[7] + E[r2*4+2]*G[11] + E[r2*4+3];
        }
        for (int i = 0; i < 12; i++) d_gpose[b*12 + i] = Ng[i];
    }
}

// ---------------- est_g ----------------
__global__ void estg_kernel() {
    int tid = threadIdx.x;
    if (tid < 8) {
        int b = tid;
        const float* g = d_gpose + b*12;
        const float* m0 = d_mean0 + b*3;
        const float* m1 = d_mean1 + b*3;
        float e[12];
        for (int r = 0; r < 3; r++) {
            e[r*4+0] = g[r*4+0]; e[r*4+1] = g[r*4+1]; e[r*4+2] = g[r*4+2];
            e[r*4+3] = -(g[r*4+0]*m1[0] + g[r*4+1]*m1[1] + g[r*4+2]*m1[2]) + g[r*4+3] + m0[r];
        }
        for (int i = 0; i < 12; i++) d_estg[b*12 + i] = e[i];
    }
}

// ---------------- loss ----------------
__global__ void loss_kernel(const float* __restrict__ p_src) {
    int bi = blockIdx.x;
    int b = bi >> 3, seg = bi & 7;
    int tid = threadIdx.x;
    int n = seg*256 + tid;
    const float* p = p_src + ((size_t)b*NN + n)*3;
    float x = p[0], y = p[1], z = p[2];
    const float* e = d_estg + b*12;
    const float* q = d_igtinv + b*12;
    float s = 0.f;
    #pragma unroll
    for (int r = 0; r < 3; r++) {
        float ae = e[r*4+0]*x + e[r*4+1]*y + e[r*4+2]*z + e[r*4+3];
        float aq = q[r*4+0]*x + q[r*4+1]*y + q[r*4+2]*z + q[r*4+3];
        s += fabsf(ae - aq);
    }
    __shared__ float sr[256];
    sr[tid] = s;
    __syncthreads();
    for (int st = 128; st; st >>= 1) {
        if (tid < st) sr[tid] += sr[tid + st];
        __syncthreads();
    }
    if (tid == 0) d_lpart[bi] = sr[0];
}

// ---------------- output ----------------
__global__ void finish_kernel(float* __restrict__ out, int out_size) {
    int i = blockIdx.x*256 + threadIdx.x;
    if (i < BB*KK && i < out_size) out[i] = d_r[i];
    if (blockIdx.x == 0 && threadIdx.x == 0 && out_size > BB*KK) {
        double s = 0.0;
        for (int j = 0; j < 64; j++) s += (double)d_lpart[j];
        out[BB*KK] = (float)(s / (double)(BB*NN*3));
    }
}

// ---------------- host ----------------
extern "C" void kernel_launch(void* const* d_in, const int* in_sizes, int n_in,
                              void* d_out, int out_size) {
    const float* p_src = (const float*)d_in[0];
    const float* p_tgt = (const float*)d_in[1];
    const float* igt   = (const float*)d_in[2];
    const float* dt    = (const float*)d_in[3];
    const float* W1    = (const float*)d_in[4];
    const float* b1    = (const float*)d_in[5];
    const float* W2    = (const float*)d_in[6];
    const float* b2    = (const float*)d_in[7];
    const float* W3    = (const float*)d_in[8];
    const float* b3    = (const float*)d_in[9];
    float* out = (float*)d_out;

    cudaFuncSetAttribute(encode_kernel<0>, cudaFuncAttributeMaxDynamicSharedMemorySize, SMEM_BYTES);
    cudaFuncSetAttribute(encode_kernel<1>, cudaFuncAttributeMaxDynamicSharedMemorySize, SMEM_BYTES);

    means_kernel<<<BB, 256>>>(p_tgt, p_src);
    setup_kernel<<<1, 32>>>(dt, igt);
    init_f_kernel<<<(BB*KK*2 + BB*6*KK + 255)/256, 256>>>();
    encode_kernel<0><<<dim3(NN/NP, BB*7), 256, SMEM_BYTES>>>(p_tgt, W1, b1, W2, b2, W3, b3);
    jh_kernel<<<BB, 256>>>(dt);
    for (int it = 0; it < 5; it++) {
        encode_kernel<1><<<dim3(NN/NP, BB), 256, SMEM_BYTES>>>(p_src, W1, b1, W2, b2, W3, b3);
        update_kernel<<<BB, 256>>>();
    }
    estg_kernel<<<1, 32>>>();
    loss_kernel<<<64, 256>>>(p_src);
    finish_kernel<<<(BB*KK + 256)/256 + 1, 256>>>(out, out_size);
}

// round 9
// speedup vs baseline: 2.1128x; 2.1128x over previous
#include <cuda_runtime.h>
#include <cuda_bf16.h>
#include <math.h>
#include <stdint.h>

#define BB 8
#define NN 2048
#define KK 1024
#define MP 128            // points per block
#define THREADS 512

// ---------------- device state ----------------
__device__ float d_mean0[BB*3], d_mean1[BB*3];
__device__ float d_posesJ[7*12];
__device__ float d_gpose[BB*12];
__device__ float d_igtinv[BB*12];
__device__ float d_estg[BB*12];
__device__ float d_f0[BB*KK], d_fj[BB*6*KK], d_f1[BB*KK];
__device__ float d_J[BB*KK*6];
__device__ float d_Hinv[BB*36];
__device__ float d_r[BB*KK];
__device__ float d_lpart[64];

// ---------------- helpers ----------------
__device__ __forceinline__ void atomicMaxF(float* addr, float val) {
    if (val >= 0.f) atomicMax((int*)addr, __float_as_int(val));
    else            atomicMin((unsigned int*)addr, __float_as_uint(val));
}
__device__ __forceinline__ void cp16(uint32_t dst, const void* src) {
    asm volatile("cp.async.cg.shared.global [%0], [%1], 16;\n" :: "r"(dst), "l"(src));
}
#define CP_COMMIT() asm volatile("cp.async.commit_group;\n" ::: "memory")

__device__ __forceinline__ uint32_t f2tf32(float f) {
    uint32_t r; asm("cvt.rna.tf32.f32 %0, %1;" : "=r"(r) : "f"(f)); return r;
}
__device__ __forceinline__ void split_tf32(float v, uint32_t& hi, uint32_t& lo) {
    hi = f2tf32(v);
    lo = f2tf32(v - __uint_as_float(hi));
}
__device__ __forceinline__ void mma_tf32(float* d,
    uint32_t a0, uint32_t a1, uint32_t a2, uint32_t a3, uint32_t b0, uint32_t b1) {
    asm volatile(
        "mma.sync.aligned.m16n8k8.row.col.f32.tf32.tf32.f32 "
        "{%0,%1,%2,%3}, {%4,%5,%6,%7}, {%8,%9}, {%0,%1,%2,%3};"
        : "+f"(d[0]), "+f"(d[1]), "+f"(d[2]), "+f"(d[3])
        : "r"(a0), "r"(a1), "r"(a2), "r"(a3), "r"(b0), "r"(b1));
}

// se3_exp (double internals), output 3x4 row-major float
__device__ void se3_exp_d(const double w[3], const double v[3], float out[12]) {
    double t2 = w[0]*w[0] + w[1]*w[1] + w[2]*w[2];
    double t = sqrt(t2);
    double A, Bc, Cc;
    if (t < 1e-6) {
        A  = 1.0 - t2/6.0;  Bc = 0.5 - t2/24.0;  Cc = 1.0/6.0 - t2/120.0;
    } else {
        double st = sin(t), ct = cos(t);
        A = st/t;  Bc = (1.0-ct)/t2;  Cc = (t-st)/(t2*t);
    }
    double W[3][3] = {{0.0,-w[2],w[1]},{w[2],0.0,-w[0]},{-w[1],w[0],0.0}};
    double W2m[3][3];
    for (int i = 0; i < 3; i++)
        for (int j = 0; j < 3; j++)
            W2m[i][j] = w[i]*w[j] - (i==j ? t2 : 0.0);
    double R[3][3], V[3][3];
    for (int i = 0; i < 3; i++)
        for (int j = 0; j < 3; j++) {
            double I = (i==j) ? 1.0 : 0.0;
            R[i][j] = I + A*W[i][j] + Bc*W2m[i][j];
            V[i][j] = I + Bc*W[i][j] + Cc*W2m[i][j];
        }
    for (int i = 0; i < 3; i++) {
        double p = V[i][0]*v[0] + V[i][1]*v[1] + V[i][2]*v[2];
        out[i*4+0] = (float)R[i][0]; out[i*4+1] = (float)R[i][1];
        out[i*4+2] = (float)R[i][2]; out[i*4+3] = (float)p;
    }
}

// ---------------- means ----------------
__global__ void means_kernel(const float* __restrict__ p_tgt, const float* __restrict__ p_src) {
    int b = blockIdx.x, tid = threadIdx.x;
    float a[6] = {0,0,0,0,0,0};
    for (int n = tid; n < NN; n += 256) {
        const float* pt = p_tgt + ((size_t)b*NN + n)*3;
        const float* ps = p_src + ((size_t)b*NN + n)*3;
        a[0] += pt[0]; a[1] += pt[1]; a[2] += pt[2];
        a[3] += ps[0]; a[4] += ps[1]; a[5] += ps[2];
    }
    for (int off = 16; off; off >>= 1)
        #pragma unroll
        for (int q = 0; q < 6; q++) a[q] += __shfl_down_sync(0xffffffffu, a[q], off);
    __shared__ float sm[8][6];
    int lane = tid & 31, w = tid >> 5;
    if (lane == 0) { for (int q = 0; q < 6; q++) sm[w][q] = a[q]; }
    __syncthreads();
    if (tid < 6) {
        float s = 0.f;
        for (int w2 = 0; w2 < 8; w2++) s += sm[w2][tid];
        s *= (1.0f / NN);
        if (tid < 3) d_mean0[b*3 + tid] = s;
        else         d_mean1[b*3 + tid - 3] = s;
    }
}

// ---------------- setup ----------------
__global__ void setup_kernel(const float* __restrict__ dt, const float* __restrict__ igt_twist) {
    int tid = threadIdx.x;
    if (tid < 7) {
        float out[12];
        if (tid == 0) {
            float I[12] = {1,0,0,0, 0,1,0,0, 0,0,1,0};
            for (int i = 0; i < 12; i++) out[i] = I[i];
        } else {
            int j = tid - 1;
            double w[3] = {0,0,0}, v[3] = {0,0,0};
            double val = -(double)__ldg(&dt[j]);
            if (j < 3) w[j] = val; else v[j-3] = val;
            se3_exp_d(w, v, out);
        }
        for (int i = 0; i < 12; i++) d_posesJ[tid*12 + i] = out[i];
    }
    if (tid >= 8 && tid < 16) {
        int b = tid - 8;
        float I[12] = {1,0,0,0, 0,1,0,0, 0,0,1,0};
        for (int i = 0; i < 12; i++) d_gpose[b*12 + i] = I[i];
    }
    if (tid >= 16 && tid < 24) {
        int b = tid - 16;
        double w[3], v[3];
        for (int i = 0; i < 3; i++) { w[i] = igt_twist[b*6 + i]; v[i] = igt_twist[b*6 + 3 + i]; }
        float g[12];
        se3_exp_d(w, v, g);
        float inv[12];
        for (int r = 0; r < 3; r++)
            for (int c = 0; c < 3; c++) inv[r*4 + c] = g[c*4 + r];
        for (int r = 0; r < 3; r++)
            inv[r*4 + 3] = -(g[0*4+r]*g[3] + g[1*4+r]*g[7] + g[2*4+r]*g[11]);
        for (int i = 0; i < 12; i++) d_igtinv[b*12 + i] = inv[i];
    }
}

__global__ void init_f_kernel() {
    int i = blockIdx.x*256 + threadIdx.x;
    if (i < BB*KK) d_f0[i] = -INFINITY;
    else if (i < BB*KK + BB*6*KK) d_fj[i - BB*KK] = -INFINITY;
    else if (i < BB*KK + BB*6*KK + BB*KK) d_f1[i - BB*KK - BB*6*KK] = -INFINITY;
}

// ---------------- fused encode via mma.sync tf32 (3xTF32 = fp32 accuracy) ----------------
// 512 threads (16 warps), 128 points. h1/h2 fp32 (phase A). Phase B:
// D[M=128, N=1024] = h2[128x128] @ W3[128x1024] via m16n8k8.tf32, 3 products.
// N in 8 chunks of 128 (W3 fp32 staged, double-buffered cp.async).
// Warp (mt = wid&7, ng = wid>>3): m-tile mt (16 rows), n-half ng (64 cols = 8 n-tiles).
// SMEM (floats):
#define OFF_B0   0          /* 128 x 136 = 17408 */
#define OFF_B1   17408
#define OFF_A    34816      /* 128 x 132 = 16896 */
#define SMEMF    51712
#define ENC_SMEM_BYTES (SMEMF*4)
#define STRB 136
#define STRA 132
// A-phase aliases (inside B0/B1 region, consumed before phase B):
#define OFF_PTS 0
#define OFF_SW1 384
#define OFF_SB1 576
#define OFF_SB2 640
#define OFF_H1  768         /* 128 x 68 = 8704 -> ends 9472 */
#define OFF_W2  9472        /* 8192 -> ends 17664 */

__device__ __forceinline__ void issue_chunk(uint32_t sbase, int ch,
                                            const float* __restrict__ W3g, int tid) {
    uint32_t buf = sbase + (uint32_t)(ch & 1) * (17408u * 4u);
    const float* src = W3g + ch*128;
    #pragma unroll
    for (int i = 0; i < 8; i++) {
        int f4 = i*512 + tid;               // 4096 cp16 = 128 rows x 32
        int row = f4 >> 5, col4 = f4 & 31;
        cp16(buf + (uint32_t)(row*STRB + col4*4)*4u, src + (size_t)row*1024 + col4*4);
    }
}

template<int MODE>
__global__ __launch_bounds__(THREADS, 1)
void encode_kernel(const float* __restrict__ P,
                   const float* __restrict__ W1g, const float* __restrict__ b1g,
                   const float* __restrict__ W2g, const float* __restrict__ b2g,
                   const float* __restrict__ W3g, const float* __restrict__ b3g) {
    extern __shared__ float sm[];
    int tid = threadIdx.x;
    int wid = tid >> 5, lane = tid & 31;
    uint32_t sbase = (uint32_t)__cvta_generic_to_shared(sm);

    int b; const float* pose; const float* mean; float* out;
    if (MODE == 0) {
        int bm = blockIdx.y;
        b = bm / 7; int m = bm % 7;
        pose = d_posesJ + m*12;
        mean = d_mean0 + b*3;
        out  = (m == 0) ? (d_f0 + b*KK) : (d_fj + ((size_t)b*6 + (m-1))*KK);
    } else {
        b = blockIdx.y;
        pose = d_gpose + b*12;
        mean = d_mean1 + b*3;
        out  = d_f1 + b*KK;
    }

    // ---- phase A0: stage small weights + transform 128 points ----
    {
        const float4* w2v = (const float4*)W2g;
        #pragma unroll
        for (int i = 0; i < 4; i++)
            *(float4*)&sm[OFF_W2 + (tid + i*512)*4] = w2v[tid + i*512];
    }
    if (tid >= 128 && tid < 320) sm[OFF_SW1 + tid - 128] = W1g[tid - 128];
    if (tid >= 320 && tid < 384) sm[OFF_SB1 + tid - 320] = b1g[tid - 320];
    if (tid >= 384 && tid < 512) sm[OFF_SB2 + tid - 384] = b2g[tid - 384];
    if (tid < MP) {
        int n = blockIdx.x * MP + tid;
        const float* pp = P + ((size_t)b*NN + n)*3;
        float dx = pp[0] - mean[0], dy = pp[1] - mean[1], dz = pp[2] - mean[2];
        sm[OFF_PTS + tid*3 + 0] = pose[0]*dx + pose[1]*dy + pose[2]*dz  + pose[3];
        sm[OFF_PTS + tid*3 + 1] = pose[4]*dx + pose[5]*dy + pose[6]*dz  + pose[7];
        sm[OFF_PTS + tid*3 + 2] = pose[8]*dx + pose[9]*dy + pose[10]*dz + pose[11];
    }
    __syncthreads();

    // ---- phase A1: h1 = relu(pt @ W1 + b1), 128 x 64, stride 68 ----
    #pragma unroll
    for (int i = 0; i < 16; i++) {
        int idx = tid + i*512;
        int p = idx >> 6, c1 = idx & 63;
        float x = sm[OFF_PTS + p*3 + 0], y = sm[OFF_PTS + p*3 + 1], z = sm[OFF_PTS + p*3 + 2];
        float v = sm[OFF_SB1 + c1];
        v = fmaf(x, sm[OFF_SW1 + c1],       v);
        v = fmaf(y, sm[OFF_SW1 + 64 + c1],  v);
        v = fmaf(z, sm[OFF_SW1 + 128 + c1], v);
        sm[OFF_H1 + p*68 + c1] = fmaxf(v, 0.f);
    }
    __syncthreads();

    // ---- phase A2: h2 = relu(h1 @ W2 + b2) -> registers ----
    // thread (p = tid>>2, rr = tid&3) owns 32 c2 (rr*4 + q*16 + j)
    float4 acc4[8];
    {
        int p = tid >> 2, rr = tid & 3;
        #pragma unroll
        for (int q = 0; q < 8; q++)
            acc4[q] = *(const float4*)&sm[OFF_SB2 + rr*4 + q*16];
        #pragma unroll
        for (int half = 0; half < 2; half++) {
            float hr[32];
            #pragma unroll
            for (int i = 0; i < 8; i++) {
                float4 h4 = *(const float4*)&sm[OFF_H1 + p*68 + half*32 + i*4];
                hr[i*4+0] = h4.x; hr[i*4+1] = h4.y; hr[i*4+2] = h4.z; hr[i*4+3] = h4.w;
            }
            #pragma unroll
            for (int q = 0; q < 8; q++) {
                int c2 = rr*4 + q*16;
                float4 a = acc4[q];
                #pragma unroll 16
                for (int c1 = 0; c1 < 32; c1++) {
                    float4 w = *(const float4*)&sm[OFF_W2 + (half*32 + c1)*128 + c2];
                    float h = hr[c1];
                    a.x = fmaf(h, w.x, a.x); a.y = fmaf(h, w.y, a.y);
                    a.z = fmaf(h, w.z, a.z); a.w = fmaf(h, w.w, a.w);
                }
                acc4[q] = a;
            }
        }
    }
    __syncthreads();   // all H1/W2 reads done; write h2 into OFF_A (separate region)
    {
        int p = tid >> 2, rr = tid & 3;
        #pragma unroll
        for (int q = 0; q < 8; q++) {
            int c2 = rr*4 + q*16;
            sm[OFF_A + p*STRA + c2 + 0] = fmaxf(acc4[q].x, 0.f);
            sm[OFF_A + p*STRA + c2 + 1] = fmaxf(acc4[q].y, 0.f);
            sm[OFF_A + p*STRA + c2 + 2] = fmaxf(acc4[q].z, 0.f);
            sm[OFF_A + p*STRA + c2 + 3] = fmaxf(acc4[q].w, 0.f);
        }
    }
    __syncthreads();   // h2 ready; B0/B1 alias region free

    issue_chunk(sbase, 0, W3g, tid); CP_COMMIT();
    issue_chunk(sbase, 1, W3g, tid); CP_COMMIT();

    // ---- phase B: 8 N-chunks of 128, warp mma tiles ----
    int mt = wid & 7, ng = wid >> 3;
    int g = lane >> 2, tg = lane & 3;
    const float* Abase = &sm[OFF_A + (mt*16)*STRA];

    for (int ch = 0; ch < 8; ch++) {
        if (ch < 7) asm volatile("cp.async.wait_group 1;\n" ::: "memory");
        else        asm volatile("cp.async.wait_group 0;\n" ::: "memory");
        __syncthreads();

        const float* Bbase = &sm[(ch & 1) ? OFF_B1 : OFF_B0] + ng*64;
        float acc[8][4];
        #pragma unroll
        for (int nt = 0; nt < 8; nt++)
            #pragma unroll
            for (int j = 0; j < 4; j++) acc[nt][j] = 0.f;

        #pragma unroll 4
        for (int ks = 0; ks < 16; ks++) {
            // A fragment (m16k8, rows g/g+8, cols tg/tg+4 of k-step)
            float av0 = Abase[g*STRA + ks*8 + tg];
            float av1 = Abase[(g+8)*STRA + ks*8 + tg];
            float av2 = Abase[g*STRA + ks*8 + tg + 4];
            float av3 = Abase[(g+8)*STRA + ks*8 + tg + 4];
            uint32_t ah0, al0, ah1, al1, ah2, al2, ah3, al3;
            split_tf32(av0, ah0, al0); split_tf32(av1, ah1, al1);
            split_tf32(av2, ah2, al2); split_tf32(av3, ah3, al3);
            const float* Bk = Bbase + (ks*8 + tg)*STRB + g;
            #pragma unroll
            for (int nt = 0; nt < 8; nt++) {
                float bv0 = Bk[nt*8];
                float bv1 = Bk[4*STRB + nt*8];
                uint32_t bh0, bl0, bh1, bl1;
                split_tf32(bv0, bh0, bl0);
                split_tf32(bv1, bh1, bl1);
                mma_tf32(acc[nt], ah0, ah1, ah2, ah3, bh0, bh1);
                mma_tf32(acc[nt], ah0, ah1, ah2, ah3, bl0, bl1);
                mma_tf32(acc[nt], al0, al1, al2, al3, bh0, bh1);
            }
        }
        __syncthreads();   // done reading buf[ch&1]
        if (ch + 2 < 8) { issue_chunk(sbase, ch + 2, W3g, tid); CP_COMMIT(); }

        // epilogue: max over 16 rows of this m-tile, then atomicMaxF across warps/CTAs
        #pragma unroll
        for (int nt = 0; nt < 8; nt++) {
            float m0 = fmaxf(acc[nt][0], acc[nt][2]);
            float m1 = fmaxf(acc[nt][1], acc[nt][3]);
            #pragma unroll
            for (int off = 4; off < 32; off <<= 1) {
                m0 = fmaxf(m0, __shfl_xor_sync(0xffffffffu, m0, off));
                m1 = fmaxf(m1, __shfl_xor_sync(0xffffffffu, m1, off));
            }
            if (g == 0) {
                int k = ch*128 + ng*64 + nt*8 + tg*2;
                atomicMaxF(&out[k],     m0 + __ldg(&b3g[k]));
                atomicMaxF(&out[k + 1], m1 + __ldg(&b3g[k + 1]));
            }
        }
    }
}

// ---------------- J and Hinv ----------------
__global__ void jh_kernel(const float* __restrict__ dt) {
    int b = blockIdx.x, tid = threadIdx.x;
    float dtv[6];
    #pragma unroll
    for (int j = 0; j < 6; j++) dtv[j] = __ldg(&dt[j]);
    double hacc[21];
    #pragma unroll
    for (int q = 0; q < 21; q++) hacc[q] = 0.0;
    for (int k = tid; k < KK; k += 256) {
        float f0k = d_f0[b*KK + k];
        float jv[6];
        #pragma unroll
        for (int j = 0; j < 6; j++) {
            jv[j] = (f0k - d_fj[((size_t)b*6 + j)*KK + k]) / dtv[j];
            d_J[((size_t)b*KK + k)*6 + j] = jv[j];
        }
        int q = 0;
        #pragma unroll
        for (int i = 0; i < 6; i++)
            #pragma unroll
            for (int j = i; j < 6; j++)
                hacc[q++] += (double)jv[i] * (double)jv[j];
    }
    for (int off = 16; off; off >>= 1)
        #pragma unroll
        for (int q = 0; q < 21; q++) hacc[q] += __shfl_down_sync(0xffffffffu, hacc[q], off);
    __shared__ double shH[8][21];
    int lane = tid & 31, w = tid >> 5;
    if (lane == 0) { for (int q = 0; q < 21; q++) shH[w][q] = hacc[q]; }
    __syncthreads();
    if (tid == 0) {
        double s[21];
        for (int q = 0; q < 21; q++) { s[q] = 0.0; for (int w2 = 0; w2 < 8; w2++) s[q] += shH[w2][q]; }
        double H[6][6];
        int q = 0;
        for (int i = 0; i < 6; i++)
            for (int j = i; j < 6; j++) { H[i][j] = s[q]; H[j][i] = s[q]; q++; }
        double M[6][12];
        for (int i = 0; i < 6; i++)
            for (int j = 0; j < 12; j++) M[i][j] = (j < 6) ? H[i][j] : ((j - 6 == i) ? 1.0 : 0.0);
        for (int col = 0; col < 6; col++) {
            int piv = col; double best = fabs(M[col][col]);
            for (int r2 = col + 1; r2 < 6; r2++)
                if (fabs(M[r2][col]) > best) { best = fabs(M[r2][col]); piv = r2; }
            if (piv != col)
                for (int j = 0; j < 12; j++) { double t = M[col][j]; M[col][j] = M[piv][j]; M[piv][j] = t; }
            double inv = 1.0 / M[col][col];
            for (int j = 0; j < 12; j++) M[col][j] *= inv;
            for (int r2 = 0; r2 < 6; r2++) {
                if (r2 == col) continue;
                double f = M[r2][col];
                for (int j = 0; j < 12; j++) M[r2][j] -= f * M[col][j];
            }
        }
        for (int i = 0; i < 6; i++)
            for (int j = 0; j < 6; j++) d_Hinv[b*36 + i*6 + j] = (float)M[i][6 + j];
    }
}

// ---------------- Gauss-Newton update (also resets f1) ----------------
__global__ void update_kernel() {
    int b = blockIdx.x, tid = threadIdx.x;
    double u[6] = {0,0,0,0,0,0};
    for (int k = tid; k < KK; k += 256) {
        float r = d_f1[b*KK + k] - d_f0[b*KK + k];
        d_r[b*KK + k] = r;
        d_f1[b*KK + k] = -INFINITY;
        #pragma unroll
        for (int j = 0; j < 6; j++) u[j] += (double)d_J[((size_t)b*KK + k)*6 + j] * (double)r;
    }
    for (int off = 16; off; off >>= 1)
        #pragma unroll
        for (int j = 0; j < 6; j++) u[j] += __shfl_down_sync(0xffffffffu, u[j], off);
    __shared__ double shU[8][6];
    int lane = tid & 31, w = tid >> 5;
    if (lane == 0) { for (int j = 0; j < 6; j++) shU[w][j] = u[j]; }
    __syncthreads();
    if (tid == 0) {
        double uu[6];
        for (int j = 0; j < 6; j++) { uu[j] = 0.0; for (int w2 = 0; w2 < 8; w2++) uu[j] += shU[w2][j]; }
        double dx[6];
        for (int i = 0; i < 6; i++) {
            double s2 = 0.0;
            for (int j = 0; j < 6; j++) s2 += (double)d_Hinv[b*36 + i*6 + j] * uu[j];
            dx[i] = -s2;
        }
        float E[12];
        double wv[3] = {dx[0], dx[1], dx[2]}, vv[3] = {dx[3], dx[4], dx[5]};
        se3_exp_d(wv, vv, E);
        float G[12];
        for (int i = 0; i < 12; i++) G[i] = d_gpose[b*12 + i];
        float Ng[12];
        for (int r2 = 0; r2 < 3; r2++) {
            for (int c = 0; c < 3; c++)
                Ng[r2*4 + c] = E[r2*4+0]*G[0*4+c] + E[r2*4+1]*G[1*4+c] + E[r2*4+2]*G[2*4+c];
            Ng[r2*4 + 3] = E[r2*4+0]*G[3] + E[r2*4+1]*G[7] + E[r2*4+2]*G[11] + E[r2*4+3];
        }
        for (int i = 0; i < 12; i++) d_gpose[b*12 + i] = Ng[i];
    }
}

// ---------------- est_g ----------------
__global__ void estg_kernel() {
    int tid = threadIdx.x;
    if (tid < 8) {
        int b = tid;
        const float* g = d_gpose + b*12;
        const float* m0 = d_mean0 + b*3;
        const float* m1 = d_mean1 + b*3;
        float e[12];
        for (int r = 0; r < 3; r++) {
            e[r*4+0] = g[r*4+0]; e[r*4+1] = g[r*4+1]; e[r*4+2] = g[r*4+2];
            e[r*4+3] = -(g[r*4+0]*m1[0] + g[r*4+1]*m1[1] + g[r*4+2]*m1[2]) + g[r*4+3] + m0[r];
        }
        for (int i = 0; i < 12; i++) d_estg[b*12 + i] = e[i];
    }
}

// ---------------- loss ----------------
__global__ void loss_kernel(const float* __restrict__ p_src) {
    int bi = blockIdx.x;
    int b = bi >> 3, seg = bi & 7;
    int tid = threadIdx.x;
    int n = seg*256 + tid;
    const float* p = p_src + ((size_t)b*NN + n)*3;
    float x = p[0], y = p[1], z = p[2];
    const float* e = d_estg + b*12;
    const float* q = d_igtinv + b*12;
    float s = 0.f;
    #pragma unroll
    for (int r = 0; r < 3; r++) {
        float ae = e[r*4+0]*x + e[r*4+1]*y + e[r*4+2]*z + e[r*4+3];
        float aq = q[r*4+0]*x + q[r*4+1]*y + q[r*4+2]*z + q[r*4+3];
        s += fabsf(ae - aq);
    }
    __shared__ float sr[256];
    sr[tid] = s;
    __syncthreads();
    for (int st = 128; st; st >>= 1) {
        if (tid < st) sr[tid] += sr[tid + st];
        __syncthreads();
    }
    if (tid == 0) d_lpart[bi] = sr[0];
}

// ---------------- output ----------------
__global__ void finish_kernel(float* __restrict__ out, int out_size) {
    int i = blockIdx.x*256 + threadIdx.x;
    if (i < BB*KK && i < out_size) out[i] = d_r[i];
    if (blockIdx.x == 0 && threadIdx.x == 0 && out_size > BB*KK) {
        double s = 0.0;
        for (int j = 0; j < 64; j++) s += (double)d_lpart[j];
        out[BB*KK] = (float)(s / (double)(BB*NN*3));
    }
}

// ---------------- host ----------------
extern "C" void kernel_launch(void* const* d_in, const int* in_sizes, int n_in,
                              void* d_out, int out_size) {
    const float* p_src = (const float*)d_in[0];
    const float* p_tgt = (const float*)d_in[1];
    const float* igt   = (const float*)d_in[2];
    const float* dt    = (const float*)d_in[3];
    const float* W1    = (const float*)d_in[4];
    const float* b1    = (const float*)d_in[5];
    const float* W2    = (const float*)d_in[6];
    const float* b2    = (const float*)d_in[7];
    const float* W3    = (const float*)d_in[8];
    const float* b3    = (const float*)d_in[9];
    float* out = (float*)d_out;

    cudaFuncSetAttribute(encode_kernel<0>, cudaFuncAttributeMaxDynamicSharedMemorySize, ENC_SMEM_BYTES);
    cudaFuncSetAttribute(encode_kernel<1>, cudaFuncAttributeMaxDynamicSharedMemorySize, ENC_SMEM_BYTES);

    means_kernel<<<BB, 256>>>(p_tgt, p_src);
    setup_kernel<<<1, 32>>>(dt, igt);
    init_f_kernel<<<(BB*KK*2 + BB*6*KK + 255)/256, 256>>>();
    encode_kernel<0><<<dim3(NN/MP, BB*7), THREADS, ENC_SMEM_BYTES>>>(p_tgt, W1, b1, W2, b2, W3, b3);
    jh_kernel<<<BB, 256>>>(dt);
    for (int it = 0; it < 5; it++) {
        encode_kernel<1><<<dim3(NN/MP, BB), THREADS, ENC_SMEM_BYTES>>>(p_src, W1, b1, W2, b2, W3, b3);
        update_kernel<<<BB, 256>>>();
    }
    estg_kernel<<<1, 32>>>();
    loss_kernel<<<64, 256>>>(p_src);
    finish_kernel<<<(BB*KK + 256)/256 + 1, 256>>>(out, out_size);
}